// round 4
// baseline (speedup 1.0000x reference)
#include <cuda_runtime.h>
#include <cuda_bf16.h>
#include <cstdint>

// Problem constants
#define B_TOT   2048
#define SEQ     49
#define CDIM    512
#define NHEAD   16
#define HD      32
#define NWIN    64
#define MROWS   (B_TOT * SEQ)      // 100352
#define QKVCOLS 1536
#define SCALE   0.17677669529663687f  // 32^-0.5

// Scratch (no cudaMalloc allowed). NOTE: device globals must ONLY be
// referenced from device code — passing them as host-side kernel args
// yields a bogus (host) address.
__device__ float g_q[(size_t)B_TOT * NHEAD * SEQ * HD];
__device__ float g_k[(size_t)B_TOT * NHEAD * SEQ * HD];
__device__ float g_v[(size_t)B_TOT * NHEAD * SEQ * HD];
__device__ float g_o[(size_t)MROWS * CDIM];

// ---------------------------------------------------------------------------
// Tiled SGEMM: C[m][n] = sum_k A[m][k] * B[n][k]   (both row-major, K inner)
// MODE 0: A = x (param), epilogue scatters into g_q/g_k/g_v (+bias, q*scale)
// MODE 1: A = g_o (device global, resolved in device code), epilogue -> Cout
// ---------------------------------------------------------------------------
#define BM 128
#define BN 128
#define BK 8
#define TM 8
#define TN 8

template <int MODE>
__global__ __launch_bounds__(256)
void sgemm_kernel(const float* __restrict__ A_param, const float* __restrict__ B,
                  const float* __restrict__ bias, float* __restrict__ Cout)
{
    __shared__ float As[BK][BM];
    __shared__ float Bs[BK][BN];

    const int tid = threadIdx.x;
    const int bm  = blockIdx.y;
    const int bn  = blockIdx.x;
    const int tx  = tid & 15;
    const int ty  = tid >> 4;
    const int K   = CDIM;

    const int ldRow  = tid >> 1;
    const int ldCol  = (tid & 1) * 4;

    // Resolve A: device-global for MODE 1 (host cannot pass g_o's address).
    const float* A = (MODE == 0) ? A_param : (const float*)g_o;

    const float* Ap = A + ((size_t)(bm * BM + ldRow)) * K + ldCol;
    const float* Bp = B + ((size_t)(bn * BN + ldRow)) * K + ldCol;

    float acc[TM][TN];
#pragma unroll
    for (int i = 0; i < TM; i++)
#pragma unroll
        for (int j = 0; j < TN; j++) acc[i][j] = 0.0f;

    for (int k0 = 0; k0 < K; k0 += BK) {
        float4 a = *reinterpret_cast<const float4*>(Ap + k0);
        float4 b = *reinterpret_cast<const float4*>(Bp + k0);
        As[ldCol + 0][ldRow] = a.x;
        As[ldCol + 1][ldRow] = a.y;
        As[ldCol + 2][ldRow] = a.z;
        As[ldCol + 3][ldRow] = a.w;
        Bs[ldCol + 0][ldRow] = b.x;
        Bs[ldCol + 1][ldRow] = b.y;
        Bs[ldCol + 2][ldRow] = b.z;
        Bs[ldCol + 3][ldRow] = b.w;
        __syncthreads();

#pragma unroll
        for (int k = 0; k < BK; k++) {
            float regM[TM], regN[TN];
#pragma unroll
            for (int i = 0; i < TM; i++) regM[i] = As[k][ty * TM + i];
#pragma unroll
            for (int j = 0; j < TN; j++) regN[j] = Bs[k][tx * TN + j];
#pragma unroll
            for (int i = 0; i < TM; i++)
#pragma unroll
                for (int j = 0; j < TN; j++)
                    acc[i][j] = fmaf(regM[i], regN[j], acc[i][j]);
        }
        __syncthreads();
    }

#pragma unroll
    for (int i = 0; i < TM; i++) {
        const int m = bm * BM + ty * TM + i;
        const int b_idx = m / SEQ;
        const int n_idx = m - b_idx * SEQ;
#pragma unroll
        for (int j = 0; j < TN; j++) {
            const int col = bn * BN + tx * TN + j;
            float val = acc[i][j] + bias[col];
            if (MODE == 0) {
                const int s = col >> 9;          // 0:q 1:k 2:v
                const int h = (col >> 5) & 15;
                const int d = col & 31;
                const size_t off = ((((size_t)b_idx * NHEAD + h) * SEQ) + n_idx) * HD + d;
                if (s == 0)      g_q[off] = val * SCALE;
                else if (s == 1) g_k[off] = val;
                else             g_v[off] = val;
            } else {
                Cout[(size_t)m * CDIM + col] = val;
            }
        }
    }
}

// ---------------------------------------------------------------------------
// Attention: one block per (head, window). 256 threads.
// ---------------------------------------------------------------------------
__global__ __launch_bounds__(256)
void attn_kernel(const float* __restrict__ mask,
                 const float* __restrict__ table,
                 const int* __restrict__ relidx)
{
    const int h = blockIdx.x;
    const int b = blockIdx.y;
    const int tid = threadIdx.x;

    __shared__ float qs[SEQ * HD];
    __shared__ float ks[SEQ * 33];
    __shared__ float vs[SEQ * 33];
    __shared__ float bmask[SEQ * SEQ];
    __shared__ float S[SEQ * SEQ];

    const size_t base = (((size_t)b * NHEAD + h) * SEQ) * HD;

    for (int i = tid; i < SEQ * HD; i += 256) {
        const int r = i >> 5, c = i & 31;
        qs[i]          = g_q[base + i];
        ks[r * 33 + c] = g_k[base + i];
        vs[r * 33 + c] = g_v[base + i];
    }
    const float* mptr = mask + (size_t)(b & (NWIN - 1)) * SEQ * SEQ;
    for (int i = tid; i < SEQ * SEQ; i += 256)
        bmask[i] = table[relidx[i] * NHEAD + h] + mptr[i];
    __syncthreads();

    for (int idx = tid; idx < SEQ * SEQ; idx += 256) {
        const int i = idx / SEQ;
        const int j = idx - i * SEQ;
        float s = 0.0f;
#pragma unroll
        for (int d = 0; d < HD; d++)
            s = fmaf(qs[i * HD + d], ks[j * 33 + d], s);
        S[idx] = s + bmask[idx];
    }
    __syncthreads();

    if (tid < SEQ) {
        float mx = -1e30f;
        for (int j = 0; j < SEQ; j++) mx = fmaxf(mx, S[tid * SEQ + j]);
        float sum = 0.0f;
        for (int j = 0; j < SEQ; j++) {
            const float e = __expf(S[tid * SEQ + j] - mx);
            S[tid * SEQ + j] = e;
            sum += e;
        }
        const float inv = 1.0f / sum;
        for (int j = 0; j < SEQ; j++) S[tid * SEQ + j] *= inv;
    }
    __syncthreads();

    for (int idx = tid; idx < SEQ * HD; idx += 256) {
        const int i = idx >> 5;
        const int d = idx & 31;
        float o = 0.0f;
#pragma unroll
        for (int j = 0; j < SEQ; j++)
            o = fmaf(S[i * SEQ + j], vs[j * 33 + d], o);
        g_o[((size_t)b * SEQ + i) * CDIM + h * HD + d] = o;
    }
}

// ---------------------------------------------------------------------------
// Identify inputs by element count (order-proof). All sizes are distinct.
// ---------------------------------------------------------------------------
extern "C" void kernel_launch(void* const* d_in, const int* in_sizes, int n_in,
                              void* d_out, int out_size)
{
    const float* x      = nullptr;
    const float* mask   = nullptr;
    const float* qkv_w  = nullptr;
    const float* qkv_b  = nullptr;
    const float* proj_w = nullptr;
    const float* proj_b = nullptr;
    const float* table  = nullptr;
    const int*   relidx = nullptr;

    for (int i = 0; i < n_in; i++) {
        switch (in_sizes[i]) {
            case 51380224: x      = (const float*)d_in[i]; break; // 2048*49*512
            case 153664:   mask   = (const float*)d_in[i]; break; // 64*49*49
            case 786432:   qkv_w  = (const float*)d_in[i]; break; // 1536*512
            case 1536:     qkv_b  = (const float*)d_in[i]; break;
            case 262144:   proj_w = (const float*)d_in[i]; break; // 512*512
            case 512:      proj_b = (const float*)d_in[i]; break;
            case 2704:     table  = (const float*)d_in[i]; break; // 169*16
            case 2401:     relidx = (const int*)  d_in[i]; break; // 49*49
            default: break;
        }
    }
    float* out = (float*)d_out;

    {
        dim3 grid(QKVCOLS / BN, MROWS / BM);   // (12, 784)
        sgemm_kernel<0><<<grid, 256>>>(x, qkv_w, qkv_b, nullptr);
    }
    {
        dim3 grid(NHEAD, B_TOT);
        attn_kernel<<<grid, 256>>>(mask, table, relidx);
    }
    {
        dim3 grid(CDIM / BN, MROWS / BM);      // (4, 784)
        sgemm_kernel<1><<<grid, 256>>>(nullptr, proj_w, proj_b, out);
    }
}

// round 6
// speedup vs baseline: 1.6074x; 1.6074x over previous
#include <cuda_runtime.h>
#include <cuda_bf16.h>
#include <cstdint>

// Problem constants
#define B_TOT   2048
#define SEQ     49
#define CDIM    512
#define NHEAD   16
#define HD      32
#define NWIN    64
#define MROWS   (B_TOT * SEQ)      // 100352
#define QKVCOLS 1536
#define SCALE   0.17677669529663687f  // 32^-0.5

// Scratch (no cudaMalloc allowed). Device globals referenced ONLY in device code.
__device__ float g_q[(size_t)B_TOT * NHEAD * SEQ * HD];
__device__ float g_k[(size_t)B_TOT * NHEAD * SEQ * HD];
__device__ float g_v[(size_t)B_TOT * NHEAD * SEQ * HD];
__device__ float g_o[(size_t)MROWS * CDIM];

// ---------------------------------------------------------------------------
// Tensor-core GEMM (bf16x3 split for ~fp32 accuracy):
//   C[m][n] = sum_k A[m][k] * B[n][k]
// Block tile 128x128, BK=32, 256 threads = 8 warps (4m x 2n), warp tile 32x64.
// mma.sync.aligned.m16n8k16.row.col.f32.bf16.bf16.f32
// Fragment loads are plain 32-bit LDS (k-pairs contiguous in both operands).
// MODE 0: A = x (param); epilogue scatters to g_q/g_k/g_v (+bias, q*SCALE)
// MODE 1: A = g_o (device global); epilogue adds bias, writes Cout
// ---------------------------------------------------------------------------
#define BK 32
#define SMS 36   // smem row stride in halves (32 + 4 pad: conflict-free frag reads)

__device__ __forceinline__ void mma_bf16(float& c0, float& c1, float& c2, float& c3,
                                         uint32_t a0, uint32_t a1, uint32_t a2, uint32_t a3,
                                         uint32_t b0, uint32_t b1)
{
    asm volatile(
        "mma.sync.aligned.m16n8k16.row.col.f32.bf16.bf16.f32 "
        "{%0,%1,%2,%3},{%4,%5,%6,%7},{%8,%9},{%0,%1,%2,%3};"
        : "+f"(c0), "+f"(c1), "+f"(c2), "+f"(c3)
        : "r"(a0), "r"(a1), "r"(a2), "r"(a3), "r"(b0), "r"(b1));
}

__device__ __forceinline__ void split_store(__nv_bfloat16* hi, __nv_bfloat16* lo, float v)
{
    __nv_bfloat16 h = __float2bfloat16(v);
    *hi = h;
    *lo = __float2bfloat16(v - __bfloat162float(h));
}

template <int MODE>
__global__ __launch_bounds__(256)
void gemm_tc(const float* __restrict__ A_param, const float* __restrict__ Bw,
             const float* __restrict__ bias, float* __restrict__ Cout)
{
    __shared__ __nv_bfloat16 Ah[128][SMS];
    __shared__ __nv_bfloat16 Al[128][SMS];
    __shared__ __nv_bfloat16 Bh[128][SMS];
    __shared__ __nv_bfloat16 Bl[128][SMS];

    const int tid  = threadIdx.x;
    const int bm   = blockIdx.y;
    const int bn   = blockIdx.x;
    const int wid  = tid >> 5;
    const int lane = tid & 31;
    const int g    = lane >> 2;     // 0..7
    const int q    = lane & 3;      // 0..3
    const int warp_m = wid & 3;     // 0..3 -> 32-row slabs
    const int warp_n = wid >> 2;    // 0..1 -> 64-col slabs

    const float* A = (MODE == 0) ? A_param : (const float*)g_o;
    const int K = CDIM;

    float acc[2][8][4];
#pragma unroll
    for (int mt = 0; mt < 2; mt++)
#pragma unroll
        for (int nt = 0; nt < 8; nt++)
#pragma unroll
            for (int r = 0; r < 4; r++) acc[mt][nt][r] = 0.0f;

    for (int k0 = 0; k0 < K; k0 += BK) {
        // Load + split A,B tiles (128x32 fp32 each) into hi/lo bf16 smem
#pragma unroll
        for (int i = 0; i < 4; i++) {
            const int t   = tid + i * 256;      // 0..1023
            const int row = t >> 3;             // 0..127
            const int c4  = (t & 7) * 4;        // 0,4,...,28
            float4 a = *reinterpret_cast<const float4*>(
                A + ((size_t)(bm * 128 + row)) * K + k0 + c4);
            float4 b = *reinterpret_cast<const float4*>(
                Bw + ((size_t)(bn * 128 + row)) * K + k0 + c4);
            split_store(&Ah[row][c4 + 0], &Al[row][c4 + 0], a.x);
            split_store(&Ah[row][c4 + 1], &Al[row][c4 + 1], a.y);
            split_store(&Ah[row][c4 + 2], &Al[row][c4 + 2], a.z);
            split_store(&Ah[row][c4 + 3], &Al[row][c4 + 3], a.w);
            split_store(&Bh[row][c4 + 0], &Bl[row][c4 + 0], b.x);
            split_store(&Bh[row][c4 + 1], &Bl[row][c4 + 1], b.y);
            split_store(&Bh[row][c4 + 2], &Bl[row][c4 + 2], b.z);
            split_store(&Bh[row][c4 + 3], &Bl[row][c4 + 3], b.w);
        }
        __syncthreads();

#pragma unroll
        for (int ks = 0; ks < BK; ks += 16) {
            // A fragments: rows warp_m*32 + mt*16 + {g, g+8}; k pairs at ks+2q, ks+2q+8
            uint32_t ah[2][4], al[2][4];
#pragma unroll
            for (int mt = 0; mt < 2; mt++) {
                const int r0 = warp_m * 32 + mt * 16 + g;
                ah[mt][0] = *reinterpret_cast<const uint32_t*>(&Ah[r0    ][ks + 2*q    ]);
                ah[mt][1] = *reinterpret_cast<const uint32_t*>(&Ah[r0 + 8][ks + 2*q    ]);
                ah[mt][2] = *reinterpret_cast<const uint32_t*>(&Ah[r0    ][ks + 2*q + 8]);
                ah[mt][3] = *reinterpret_cast<const uint32_t*>(&Ah[r0 + 8][ks + 2*q + 8]);
                al[mt][0] = *reinterpret_cast<const uint32_t*>(&Al[r0    ][ks + 2*q    ]);
                al[mt][1] = *reinterpret_cast<const uint32_t*>(&Al[r0 + 8][ks + 2*q    ]);
                al[mt][2] = *reinterpret_cast<const uint32_t*>(&Al[r0    ][ks + 2*q + 8]);
                al[mt][3] = *reinterpret_cast<const uint32_t*>(&Al[r0 + 8][ks + 2*q + 8]);
            }
            // B fragments: n rows warp_n*64 + nt*8 + g; k pairs at ks+2q, ks+2q+8
            uint32_t bh[8][2], bl[8][2];
#pragma unroll
            for (int nt = 0; nt < 8; nt++) {
                const int n0 = warp_n * 64 + nt * 8 + g;
                bh[nt][0] = *reinterpret_cast<const uint32_t*>(&Bh[n0][ks + 2*q    ]);
                bh[nt][1] = *reinterpret_cast<const uint32_t*>(&Bh[n0][ks + 2*q + 8]);
                bl[nt][0] = *reinterpret_cast<const uint32_t*>(&Bl[n0][ks + 2*q    ]);
                bl[nt][1] = *reinterpret_cast<const uint32_t*>(&Bl[n0][ks + 2*q + 8]);
            }
#pragma unroll
            for (int mt = 0; mt < 2; mt++)
#pragma unroll
                for (int nt = 0; nt < 8; nt++) {
                    float* c = acc[mt][nt];
                    mma_bf16(c[0], c[1], c[2], c[3],
                             ah[mt][0], ah[mt][1], ah[mt][2], ah[mt][3],
                             bh[nt][0], bh[nt][1]);
                    mma_bf16(c[0], c[1], c[2], c[3],
                             ah[mt][0], ah[mt][1], ah[mt][2], ah[mt][3],
                             bl[nt][0], bl[nt][1]);
                    mma_bf16(c[0], c[1], c[2], c[3],
                             al[mt][0], al[mt][1], al[mt][2], al[mt][3],
                             bh[nt][0], bh[nt][1]);
                }
        }
        __syncthreads();
    }

    // Epilogue: C[g-row][2q, 2q+1] pairs; rows {m0, m0+8}
#pragma unroll
    for (int mt = 0; mt < 2; mt++) {
        const int m0 = bm * 128 + warp_m * 32 + mt * 16 + g;
#pragma unroll
        for (int nt = 0; nt < 8; nt++) {
            const int col0 = bn * 128 + warp_n * 64 + nt * 8 + 2 * q;
#pragma unroll
            for (int half = 0; half < 2; half++) {     // c0,c1 vs c2,c3
                const int m = m0 + half * 8;
                const int b_idx = m / SEQ;
                const int n_idx = m - b_idx * SEQ;
#pragma unroll
                for (int e = 0; e < 2; e++) {
                    const int col = col0 + e;
                    float val = acc[mt][nt][half * 2 + e] + bias[col];
                    if (MODE == 0) {
                        const int s = col >> 9;          // 0:q 1:k 2:v
                        const int h = (col >> 5) & 15;
                        const int d = col & 31;
                        const size_t off =
                            ((((size_t)b_idx * NHEAD + h) * SEQ) + n_idx) * HD + d;
                        if (s == 0)      g_q[off] = val * SCALE;
                        else if (s == 1) g_k[off] = val;
                        else             g_v[off] = val;
                    } else {
                        Cout[(size_t)m * CDIM + col] = val;
                    }
                }
            }
        }
    }
}

// ---------------------------------------------------------------------------
// Attention: one block per (head, window). 256 threads. (unchanged)
// ---------------------------------------------------------------------------
__global__ __launch_bounds__(256)
void attn_kernel(const float* __restrict__ mask,
                 const float* __restrict__ table,
                 const int* __restrict__ relidx)
{
    const int h = blockIdx.x;
    const int b = blockIdx.y;
    const int tid = threadIdx.x;

    __shared__ float qs[SEQ * HD];
    __shared__ float ks[SEQ * 33];
    __shared__ float vs[SEQ * 33];
    __shared__ float bmask[SEQ * SEQ];
    __shared__ float S[SEQ * SEQ];

    const size_t base = (((size_t)b * NHEAD + h) * SEQ) * HD;

    for (int i = tid; i < SEQ * HD; i += 256) {
        const int r = i >> 5, c = i & 31;
        qs[i]          = g_q[base + i];
        ks[r * 33 + c] = g_k[base + i];
        vs[r * 33 + c] = g_v[base + i];
    }
    const float* mptr = mask + (size_t)(b & (NWIN - 1)) * SEQ * SEQ;
    for (int i = tid; i < SEQ * SEQ; i += 256)
        bmask[i] = table[relidx[i] * NHEAD + h] + mptr[i];
    __syncthreads();

    for (int idx = tid; idx < SEQ * SEQ; idx += 256) {
        const int i = idx / SEQ;
        const int j = idx - i * SEQ;
        float s = 0.0f;
#pragma unroll
        for (int d = 0; d < HD; d++)
            s = fmaf(qs[i * HD + d], ks[j * 33 + d], s);
        S[idx] = s + bmask[idx];
    }
    __syncthreads();

    if (tid < SEQ) {
        float mx = -1e30f;
        for (int j = 0; j < SEQ; j++) mx = fmaxf(mx, S[tid * SEQ + j]);
        float sum = 0.0f;
        for (int j = 0; j < SEQ; j++) {
            const float e = __expf(S[tid * SEQ + j] - mx);
            S[tid * SEQ + j] = e;
            sum += e;
        }
        const float inv = 1.0f / sum;
        for (int j = 0; j < SEQ; j++) S[tid * SEQ + j] *= inv;
    }
    __syncthreads();

    for (int idx = tid; idx < SEQ * HD; idx += 256) {
        const int i = idx >> 5;
        const int d = idx & 31;
        float o = 0.0f;
#pragma unroll
        for (int j = 0; j < SEQ; j++)
            o = fmaf(S[i * SEQ + j], vs[j * 33 + d], o);
        g_o[((size_t)b * SEQ + i) * CDIM + h * HD + d] = o;
    }
}

// ---------------------------------------------------------------------------
// Identify inputs by element count (order-proof). All sizes are distinct.
// ---------------------------------------------------------------------------
extern "C" void kernel_launch(void* const* d_in, const int* in_sizes, int n_in,
                              void* d_out, int out_size)
{
    const float* x      = nullptr;
    const float* mask   = nullptr;
    const float* qkv_w  = nullptr;
    const float* qkv_b  = nullptr;
    const float* proj_w = nullptr;
    const float* proj_b = nullptr;
    const float* table  = nullptr;
    const int*   relidx = nullptr;

    for (int i = 0; i < n_in; i++) {
        switch (in_sizes[i]) {
            case 51380224: x      = (const float*)d_in[i]; break;
            case 153664:   mask   = (const float*)d_in[i]; break;
            case 786432:   qkv_w  = (const float*)d_in[i]; break;
            case 1536:     qkv_b  = (const float*)d_in[i]; break;
            case 262144:   proj_w = (const float*)d_in[i]; break;
            case 512:      proj_b = (const float*)d_in[i]; break;
            case 2704:     table  = (const float*)d_in[i]; break;
            case 2401:     relidx = (const int*)  d_in[i]; break;
            default: break;
        }
    }
    float* out = (float*)d_out;

    {
        dim3 grid(QKVCOLS / 128, MROWS / 128);   // (12, 784)
        gemm_tc<0><<<grid, 256>>>(x, qkv_w, qkv_b, nullptr);
    }
    {
        dim3 grid(NHEAD, B_TOT);
        attn_kernel<<<grid, 256>>>(mask, table, relidx);
    }
    {
        dim3 grid(CDIM / 128, MROWS / 128);      // (4, 784)
        gemm_tc<1><<<grid, 256>>>(nullptr, proj_w, proj_b, out);
    }
}

// round 7
// speedup vs baseline: 2.0948x; 1.3032x over previous
#include <cuda_runtime.h>
#include <cuda_bf16.h>
#include <cstdint>

// Problem constants
#define B_TOT   2048
#define SEQ     49
#define CDIM    512
#define NHEAD   16
#define HD      32
#define NWIN    64
#define MROWS   (B_TOT * SEQ)      // 100352
#define QKVCOLS 1536
#define SCALE   0.17677669529663687f  // 32^-0.5

// Scratch (no cudaMalloc). Device globals referenced ONLY in device code.
__device__ float g_q[(size_t)B_TOT * NHEAD * SEQ * HD];
__device__ float g_k[(size_t)B_TOT * NHEAD * SEQ * HD];
__device__ float g_v[(size_t)B_TOT * NHEAD * SEQ * HD];

// Pre-split bf16 operands (hi/lo) for the bf16x3 GEMMs
__device__ __nv_bfloat16 gx_h[(size_t)MROWS * CDIM];
__device__ __nv_bfloat16 gx_l[(size_t)MROWS * CDIM];
__device__ __nv_bfloat16 g_oh[(size_t)MROWS * CDIM];
__device__ __nv_bfloat16 g_ol[(size_t)MROWS * CDIM];
__device__ __nv_bfloat16 w_qkvh[(size_t)QKVCOLS * CDIM];
__device__ __nv_bfloat16 w_qkvl[(size_t)QKVCOLS * CDIM];
__device__ __nv_bfloat16 w_projh[(size_t)CDIM * CDIM];
__device__ __nv_bfloat16 w_projl[(size_t)CDIM * CDIM];

// ---------------------------------------------------------------------------
// fp32 -> (hi,lo) bf16 split conversion, vectorized. WHICH: 0=x 1=qkv_w 2=proj_w
// ---------------------------------------------------------------------------
template <int WHICH>
__global__ __launch_bounds__(256)
void convert_split(const float* __restrict__ src)
{
    const size_t i = (size_t)blockIdx.x * blockDim.x + threadIdx.x; // float4 idx
    float4 v = reinterpret_cast<const float4*>(src)[i];

    __nv_bfloat16 hx = __float2bfloat16(v.x);
    __nv_bfloat16 hy = __float2bfloat16(v.y);
    __nv_bfloat16 hz = __float2bfloat16(v.z);
    __nv_bfloat16 hw = __float2bfloat16(v.w);
    __nv_bfloat16 lx = __float2bfloat16(v.x - __bfloat162float(hx));
    __nv_bfloat16 ly = __float2bfloat16(v.y - __bfloat162float(hy));
    __nv_bfloat16 lz = __float2bfloat16(v.z - __bfloat162float(hz));
    __nv_bfloat16 lw = __float2bfloat16(v.w - __bfloat162float(hw));

    __nv_bfloat162 hp0 = __halves2bfloat162(hx, hy);
    __nv_bfloat162 hp1 = __halves2bfloat162(hz, hw);
    __nv_bfloat162 lp0 = __halves2bfloat162(lx, ly);
    __nv_bfloat162 lp1 = __halves2bfloat162(lz, lw);

    uint2 H, L;
    H.x = *reinterpret_cast<uint32_t*>(&hp0);
    H.y = *reinterpret_cast<uint32_t*>(&hp1);
    L.x = *reinterpret_cast<uint32_t*>(&lp0);
    L.y = *reinterpret_cast<uint32_t*>(&lp1);

    __nv_bfloat16 *dh, *dl;
    if (WHICH == 0)      { dh = gx_h;   dl = gx_l;   }
    else if (WHICH == 1) { dh = w_qkvh; dl = w_qkvl; }
    else                 { dh = w_projh; dl = w_projl; }
    reinterpret_cast<uint2*>(dh)[i] = H;
    reinterpret_cast<uint2*>(dl)[i] = L;
}

// ---------------------------------------------------------------------------
// Tensor-core GEMM, bf16x3, pre-split operands, cp.async 2-stage + ldmatrix.
//   C[m][n] = sum_k A[m][k] * B[n][k]
// Block tile 128x128, BK=32, 256 threads = 8 warps (4m x 2n), warp tile 32x64.
// MODE 0: A = gx_*, B = w_qkv*; scatter epilogue to g_q/g_k/g_v
// MODE 1: A = g_o*, B = w_proj*; epilogue adds bias -> Cout
// ---------------------------------------------------------------------------
#define ROWB 80                         // smem row stride (bytes): 64 data + 16 pad (odd/16)
#define TILE_BYTES (128 * ROWB)         // 10240
#define STAGE_BYTES (4 * TILE_BYTES)    // 40960
#define SMEM_DYN (2 * STAGE_BYTES)      // 81920

__device__ __forceinline__ void mma_bf16(float& c0, float& c1, float& c2, float& c3,
                                         uint32_t a0, uint32_t a1, uint32_t a2, uint32_t a3,
                                         uint32_t b0, uint32_t b1)
{
    asm volatile(
        "mma.sync.aligned.m16n8k16.row.col.f32.bf16.bf16.f32 "
        "{%0,%1,%2,%3},{%4,%5,%6,%7},{%8,%9},{%0,%1,%2,%3};"
        : "+f"(c0), "+f"(c1), "+f"(c2), "+f"(c3)
        : "r"(a0), "r"(a1), "r"(a2), "r"(a3), "r"(b0), "r"(b1));
}

__device__ __forceinline__ void ldsm4(uint32_t& r0, uint32_t& r1, uint32_t& r2, uint32_t& r3,
                                      uint32_t addr)
{
    asm volatile("ldmatrix.sync.aligned.m8n8.x4.shared.b16 {%0,%1,%2,%3},[%4];"
                 : "=r"(r0), "=r"(r1), "=r"(r2), "=r"(r3) : "r"(addr));
}

__device__ __forceinline__ void cp16(uint32_t dst, const void* src)
{
    asm volatile("cp.async.cg.shared.global [%0], [%1], 16;" :: "r"(dst), "l"(src));
}

template <int MODE>
__global__ __launch_bounds__(256, 2)
void gemm_tc(const float* __restrict__ bias, float* __restrict__ Cout)
{
    extern __shared__ char smem[];
    const uint32_t smem_base = (uint32_t)__cvta_generic_to_shared(smem);

    const int tid  = threadIdx.x;
    const int bm   = blockIdx.y;
    const int bn   = blockIdx.x;
    const int lane = tid & 31;
    const int wid  = tid >> 5;
    const int warp_m = wid & 3;
    const int warp_n = wid >> 2;

    const __nv_bfloat16* Ah = (MODE == 0) ? gx_h : g_oh;
    const __nv_bfloat16* Al = (MODE == 0) ? gx_l : g_ol;
    const __nv_bfloat16* Bh = (MODE == 0) ? w_qkvh : w_projh;
    const __nv_bfloat16* Bl = (MODE == 0) ? w_qkvl : w_projl;

    float acc[2][8][4];
#pragma unroll
    for (int mt = 0; mt < 2; mt++)
#pragma unroll
        for (int nt = 0; nt < 8; nt++)
#pragma unroll
            for (int r = 0; r < 4; r++) acc[mt][nt][r] = 0.0f;

    // ---- stage loader: 8 cp.async of 16B per thread ----
    auto load_stage = [&](int stage, int k0) {
#pragma unroll
        for (int j = 0; j < 2; j++) {
            const int c   = tid * 2 + j;       // 0..511
            const int row = c >> 2;            // 0..127
            const int c16 = c & 3;             // 16B chunk within 64B row
            const size_t aoff = (size_t)(bm * 128 + row) * CDIM + k0 + c16 * 8;
            const size_t boff = (size_t)(bn * 128 + row) * CDIM + k0 + c16 * 8;
            const uint32_t d = smem_base + stage * STAGE_BYTES + row * ROWB + c16 * 16;
            cp16(d,                  Ah + aoff);
            cp16(d + TILE_BYTES,     Al + aoff);
            cp16(d + 2 * TILE_BYTES, Bh + boff);
            cp16(d + 3 * TILE_BYTES, Bl + boff);
        }
    };

    // ---- compute one 128x128x32 stage ----
    auto compute_stage = [&](int stage) {
        const uint32_t sb = smem_base + stage * STAGE_BYTES;
#pragma unroll
        for (int ks = 0; ks < 32; ks += 16) {
            uint32_t ah[2][4], al[2][4];
#pragma unroll
            for (int mt = 0; mt < 2; mt++) {
                const uint32_t rowA = warp_m * 32 + mt * 16 + (lane & 15);
                const uint32_t addr = sb + rowA * ROWB + ks * 2 + (lane >> 4) * 16;
                ldsm4(ah[mt][0], ah[mt][1], ah[mt][2], ah[mt][3], addr);
                ldsm4(al[mt][0], al[mt][1], al[mt][2], al[mt][3], addr + TILE_BYTES);
            }
#pragma unroll
            for (int j = 0; j < 4; j++) {
                const uint32_t rowB = warp_n * 64 + (2 * j + (lane >> 4)) * 8 + (lane & 7);
                const uint32_t addr = sb + 2 * TILE_BYTES + rowB * ROWB + ks * 2
                                      + ((lane >> 3) & 1) * 16;
                uint32_t bh0, bh1, bh2, bh3, bl0, bl1, bl2, bl3;
                ldsm4(bh0, bh1, bh2, bh3, addr);
                ldsm4(bl0, bl1, bl2, bl3, addr + TILE_BYTES);
#pragma unroll
                for (int mt = 0; mt < 2; mt++) {
                    float* c0 = acc[mt][2 * j];
                    mma_bf16(c0[0], c0[1], c0[2], c0[3],
                             ah[mt][0], ah[mt][1], ah[mt][2], ah[mt][3], bh0, bh1);
                    mma_bf16(c0[0], c0[1], c0[2], c0[3],
                             ah[mt][0], ah[mt][1], ah[mt][2], ah[mt][3], bl0, bl1);
                    mma_bf16(c0[0], c0[1], c0[2], c0[3],
                             al[mt][0], al[mt][1], al[mt][2], al[mt][3], bh0, bh1);
                    float* c1 = acc[mt][2 * j + 1];
                    mma_bf16(c1[0], c1[1], c1[2], c1[3],
                             ah[mt][0], ah[mt][1], ah[mt][2], ah[mt][3], bh2, bh3);
                    mma_bf16(c1[0], c1[1], c1[2], c1[3],
                             ah[mt][0], ah[mt][1], ah[mt][2], ah[mt][3], bl2, bl3);
                    mma_bf16(c1[0], c1[1], c1[2], c1[3],
                             al[mt][0], al[mt][1], al[mt][2], al[mt][3], bh2, bh3);
                }
            }
        }
    };

    const int KT = CDIM / 32;   // 16
    load_stage(0, 0);
    asm volatile("cp.async.commit_group;" ::: "memory");

    for (int kt = 0; kt < KT; kt++) {
        asm volatile("cp.async.wait_group 0;" ::: "memory");
        __syncthreads();
        if (kt + 1 < KT) {
            load_stage((kt + 1) & 1, (kt + 1) * 32);
            asm volatile("cp.async.commit_group;" ::: "memory");
        }
        compute_stage(kt & 1);
        __syncthreads();
    }

    // Epilogue (fragment layout identical to validated R6 kernel)
    const int g = lane >> 2;
    const int q = lane & 3;
#pragma unroll
    for (int mt = 0; mt < 2; mt++) {
        const int m0 = bm * 128 + warp_m * 32 + mt * 16 + g;
#pragma unroll
        for (int nt = 0; nt < 8; nt++) {
            const int col0 = bn * 128 + warp_n * 64 + nt * 8 + 2 * q;
#pragma unroll
            for (int half = 0; half < 2; half++) {
                const int m = m0 + half * 8;
                const int b_idx = m / SEQ;
                const int n_idx = m - b_idx * SEQ;
#pragma unroll
                for (int e = 0; e < 2; e++) {
                    const int col = col0 + e;
                    float val = acc[mt][nt][half * 2 + e] + bias[col];
                    if (MODE == 0) {
                        const int s = col >> 9;          // 0:q 1:k 2:v
                        const int h = (col >> 5) & 15;
                        const int d = col & 31;
                        const size_t off =
                            ((((size_t)b_idx * NHEAD + h) * SEQ) + n_idx) * HD + d;
                        if (s == 0)      g_q[off] = val * SCALE;
                        else if (s == 1) g_k[off] = val;
                        else             g_v[off] = val;
                    } else {
                        Cout[(size_t)m * CDIM + col] = val;
                    }
                }
            }
        }
    }
}

// ---------------------------------------------------------------------------
// Attention: one block per (head, window). 256 threads.
// Output emitted directly as hi/lo bf16 split for the proj GEMM.
// ---------------------------------------------------------------------------
__global__ __launch_bounds__(256)
void attn_kernel(const float* __restrict__ mask,
                 const float* __restrict__ table,
                 const int* __restrict__ relidx)
{
    const int h = blockIdx.x;
    const int b = blockIdx.y;
    const int tid = threadIdx.x;

    __shared__ float qs[SEQ * HD];
    __shared__ float ks[SEQ * 33];
    __shared__ float vs[SEQ * 33];
    __shared__ float bmask[SEQ * SEQ];
    __shared__ float S[SEQ * SEQ];

    const size_t base = (((size_t)b * NHEAD + h) * SEQ) * HD;

    for (int i = tid; i < SEQ * HD; i += 256) {
        const int r = i >> 5, c = i & 31;
        qs[i]          = g_q[base + i];
        ks[r * 33 + c] = g_k[base + i];
        vs[r * 33 + c] = g_v[base + i];
    }
    const float* mptr = mask + (size_t)(b & (NWIN - 1)) * SEQ * SEQ;
    for (int i = tid; i < SEQ * SEQ; i += 256)
        bmask[i] = table[relidx[i] * NHEAD + h] + mptr[i];
    __syncthreads();

    for (int idx = tid; idx < SEQ * SEQ; idx += 256) {
        const int i = idx / SEQ;
        const int j = idx - i * SEQ;
        float s = 0.0f;
#pragma unroll
        for (int d = 0; d < HD; d++)
            s = fmaf(qs[i * HD + d], ks[j * 33 + d], s);
        S[idx] = s + bmask[idx];
    }
    __syncthreads();

    if (tid < SEQ) {
        float mx = -1e30f;
        for (int j = 0; j < SEQ; j++) mx = fmaxf(mx, S[tid * SEQ + j]);
        float sum = 0.0f;
        for (int j = 0; j < SEQ; j++) {
            const float e = __expf(S[tid * SEQ + j] - mx);
            S[tid * SEQ + j] = e;
            sum += e;
        }
        const float inv = 1.0f / sum;
        for (int j = 0; j < SEQ; j++) S[tid * SEQ + j] *= inv;
    }
    __syncthreads();

    for (int idx = tid; idx < SEQ * HD; idx += 256) {
        const int i = idx >> 5;
        const int d = idx & 31;
        float o = 0.0f;
#pragma unroll
        for (int j = 0; j < SEQ; j++)
            o = fmaf(S[i * SEQ + j], vs[j * 33 + d], o);
        const size_t oo = ((size_t)b * SEQ + i) * CDIM + h * HD + d;
        __nv_bfloat16 hi = __float2bfloat16(o);
        g_oh[oo] = hi;
        g_ol[oo] = __float2bfloat16(o - __bfloat162float(hi));
    }
}

// ---------------------------------------------------------------------------
extern "C" void kernel_launch(void* const* d_in, const int* in_sizes, int n_in,
                              void* d_out, int out_size)
{
    const float* x      = nullptr;
    const float* mask   = nullptr;
    const float* qkv_w  = nullptr;
    const float* qkv_b  = nullptr;
    const float* proj_w = nullptr;
    const float* proj_b = nullptr;
    const float* table  = nullptr;
    const int*   relidx = nullptr;

    for (int i = 0; i < n_in; i++) {
        switch (in_sizes[i]) {
            case 51380224: x      = (const float*)d_in[i]; break;
            case 153664:   mask   = (const float*)d_in[i]; break;
            case 786432:   qkv_w  = (const float*)d_in[i]; break;
            case 1536:     qkv_b  = (const float*)d_in[i]; break;
            case 262144:   proj_w = (const float*)d_in[i]; break;
            case 512:      proj_b = (const float*)d_in[i]; break;
            case 2704:     table  = (const float*)d_in[i]; break;
            case 2401:     relidx = (const int*)  d_in[i]; break;
            default: break;
        }
    }
    float* out = (float*)d_out;

    cudaFuncSetAttribute(gemm_tc<0>, cudaFuncAttributeMaxDynamicSharedMemorySize, SMEM_DYN);
    cudaFuncSetAttribute(gemm_tc<1>, cudaFuncAttributeMaxDynamicSharedMemorySize, SMEM_DYN);

    // Pre-split conversions (hi/lo bf16)
    convert_split<0><<<(MROWS * CDIM / 4) / 256, 256>>>(x);          // 50176 blocks
    convert_split<1><<<(QKVCOLS * CDIM / 4) / 256, 256>>>(qkv_w);    // 768
    convert_split<2><<<(CDIM * CDIM / 4) / 256, 256>>>(proj_w);      // 256

    {
        dim3 grid(QKVCOLS / 128, MROWS / 128);   // (12, 784)
        gemm_tc<0><<<grid, 256, SMEM_DYN>>>(qkv_b, nullptr);
    }
    {
        dim3 grid(NHEAD, B_TOT);
        attn_kernel<<<grid, 256>>>(mask, table, relidx);
    }
    {
        dim3 grid(CDIM / 128, MROWS / 128);      // (4, 784)
        gemm_tc<1><<<grid, 256, SMEM_DYN>>>(proj_b, out);
    }
}

// round 9
// speedup vs baseline: 2.2592x; 1.0785x over previous
#include <cuda_runtime.h>
#include <cuda_bf16.h>
#include <cstdint>

// Problem constants
#define B_TOT   2048
#define SEQ     49
#define CDIM    512
#define NHEAD   16
#define HD      32
#define NWIN    64
#define MROWS   (B_TOT * SEQ)      // 100352
#define QKVCOLS 1536
#define SCALE   0.17677669529663687f  // 32^-0.5

// Scratch (no cudaMalloc). Device globals referenced ONLY in device code.
__device__ float g_q[(size_t)B_TOT * NHEAD * SEQ * HD];
__device__ float g_k[(size_t)B_TOT * NHEAD * SEQ * HD];
__device__ float g_v[(size_t)B_TOT * NHEAD * SEQ * HD];

// Pre-split bf16 operands (hi/lo) for the bf16x3 GEMMs
__device__ __nv_bfloat16 gx_h[(size_t)MROWS * CDIM];
__device__ __nv_bfloat16 gx_l[(size_t)MROWS * CDIM];
__device__ __nv_bfloat16 g_oh[(size_t)MROWS * CDIM];
__device__ __nv_bfloat16 g_ol[(size_t)MROWS * CDIM];
__device__ __nv_bfloat16 w_qkvh[(size_t)QKVCOLS * CDIM];
__device__ __nv_bfloat16 w_qkvl[(size_t)QKVCOLS * CDIM];
__device__ __nv_bfloat16 w_projh[(size_t)CDIM * CDIM];
__device__ __nv_bfloat16 w_projl[(size_t)CDIM * CDIM];

// ---------------------------------------------------------------------------
// fp32 -> (hi,lo) bf16 split conversion. WHICH: 0=x 1=qkv_w 2=proj_w
// ---------------------------------------------------------------------------
template <int WHICH>
__global__ __launch_bounds__(256)
void convert_split(const float* __restrict__ src)
{
    const size_t i = (size_t)blockIdx.x * blockDim.x + threadIdx.x; // float4 idx
    float4 v = reinterpret_cast<const float4*>(src)[i];

    __nv_bfloat16 hx = __float2bfloat16(v.x);
    __nv_bfloat16 hy = __float2bfloat16(v.y);
    __nv_bfloat16 hz = __float2bfloat16(v.z);
    __nv_bfloat16 hw = __float2bfloat16(v.w);
    __nv_bfloat16 lx = __float2bfloat16(v.x - __bfloat162float(hx));
    __nv_bfloat16 ly = __float2bfloat16(v.y - __bfloat162float(hy));
    __nv_bfloat16 lz = __float2bfloat16(v.z - __bfloat162float(hz));
    __nv_bfloat16 lw = __float2bfloat16(v.w - __bfloat162float(hw));

    __nv_bfloat162 hp0 = __halves2bfloat162(hx, hy);
    __nv_bfloat162 hp1 = __halves2bfloat162(hz, hw);
    __nv_bfloat162 lp0 = __halves2bfloat162(lx, ly);
    __nv_bfloat162 lp1 = __halves2bfloat162(lz, lw);

    uint2 H, L;
    H.x = *reinterpret_cast<uint32_t*>(&hp0);
    H.y = *reinterpret_cast<uint32_t*>(&hp1);
    L.x = *reinterpret_cast<uint32_t*>(&lp0);
    L.y = *reinterpret_cast<uint32_t*>(&lp1);

    __nv_bfloat16 *dh, *dl;
    if (WHICH == 0)      { dh = gx_h;   dl = gx_l;   }
    else if (WHICH == 1) { dh = w_qkvh; dl = w_qkvl; }
    else                 { dh = w_projh; dl = w_projl; }
    reinterpret_cast<uint2*>(dh)[i] = H;
    reinterpret_cast<uint2*>(dl)[i] = L;
}

// ---------------------------------------------------------------------------
// Tensor-core GEMM (validated R7 structure), bf16x3, cp.async 2-stage + ldmatrix.
//   C[m][n] = sum_k A[m][k] * B[n][k]
// Block tile 128x128, BK=32, 256 threads = 8 warps (4m x 2n), warp tile 32x64.
// One __syncthreads per k-tile (wait_group+sync proves other buffer is free).
// ---------------------------------------------------------------------------
#define ROWB 80                         // smem row stride (bytes): 64 data + 16 pad
#define TILE_BYTES (128 * ROWB)         // 10240
#define STAGE_BYTES (4 * TILE_BYTES)    // 40960
#define SMEM_DYN (2 * STAGE_BYTES)      // 81920

__device__ __forceinline__ void mma_bf16(float& c0, float& c1, float& c2, float& c3,
                                         uint32_t a0, uint32_t a1, uint32_t a2, uint32_t a3,
                                         uint32_t b0, uint32_t b1)
{
    asm volatile(
        "mma.sync.aligned.m16n8k16.row.col.f32.bf16.bf16.f32 "
        "{%0,%1,%2,%3},{%4,%5,%6,%7},{%8,%9},{%0,%1,%2,%3};"
        : "+f"(c0), "+f"(c1), "+f"(c2), "+f"(c3)
        : "r"(a0), "r"(a1), "r"(a2), "r"(a3), "r"(b0), "r"(b1));
}

__device__ __forceinline__ void ldsm4(uint32_t& r0, uint32_t& r1, uint32_t& r2, uint32_t& r3,
                                      uint32_t addr)
{
    asm volatile("ldmatrix.sync.aligned.m8n8.x4.shared.b16 {%0,%1,%2,%3},[%4];"
                 : "=r"(r0), "=r"(r1), "=r"(r2), "=r"(r3) : "r"(addr));
}

__device__ __forceinline__ void cp16(uint32_t dst, const void* src)
{
    asm volatile("cp.async.cg.shared.global [%0], [%1], 16;" :: "r"(dst), "l"(src));
}

template <int MODE>
__global__ __launch_bounds__(256, 2)
void gemm_tc(const float* __restrict__ bias, float* __restrict__ Cout)
{
    extern __shared__ char smem[];
    const uint32_t smem_base = (uint32_t)__cvta_generic_to_shared(smem);

    const int tid  = threadIdx.x;
    const int bm   = blockIdx.y;
    const int bn   = blockIdx.x;
    const int lane = tid & 31;
    const int wid  = tid >> 5;
    const int warp_m = wid & 3;
    const int warp_n = wid >> 2;

    const __nv_bfloat16* Ah = (MODE == 0) ? gx_h : g_oh;
    const __nv_bfloat16* Al = (MODE == 0) ? gx_l : g_ol;
    const __nv_bfloat16* Bh = (MODE == 0) ? w_qkvh : w_projh;
    const __nv_bfloat16* Bl = (MODE == 0) ? w_qkvl : w_projl;

    float acc[2][8][4];
#pragma unroll
    for (int mt = 0; mt < 2; mt++)
#pragma unroll
        for (int nt = 0; nt < 8; nt++)
#pragma unroll
            for (int r = 0; r < 4; r++) acc[mt][nt][r] = 0.0f;

    auto load_stage = [&](int stage, int k0) {
#pragma unroll
        for (int j = 0; j < 2; j++) {
            const int c   = tid * 2 + j;       // 0..511
            const int row = c >> 2;            // 0..127
            const int c16 = c & 3;             // 16B chunk within 64B row
            const size_t aoff = (size_t)(bm * 128 + row) * CDIM + k0 + c16 * 8;
            const size_t boff = (size_t)(bn * 128 + row) * CDIM + k0 + c16 * 8;
            const uint32_t d = smem_base + stage * STAGE_BYTES + row * ROWB + c16 * 16;
            cp16(d,                  Ah + aoff);
            cp16(d + TILE_BYTES,     Al + aoff);
            cp16(d + 2 * TILE_BYTES, Bh + boff);
            cp16(d + 3 * TILE_BYTES, Bl + boff);
        }
    };

    auto compute_stage = [&](int stage) {
        const uint32_t sb = smem_base + stage * STAGE_BYTES;
#pragma unroll
        for (int ks = 0; ks < 32; ks += 16) {
            uint32_t ah[2][4], al[2][4];
#pragma unroll
            for (int mt = 0; mt < 2; mt++) {
                const uint32_t rowA = warp_m * 32 + mt * 16 + (lane & 15);
                const uint32_t addr = sb + rowA * ROWB + ks * 2 + (lane >> 4) * 16;
                ldsm4(ah[mt][0], ah[mt][1], ah[mt][2], ah[mt][3], addr);
                ldsm4(al[mt][0], al[mt][1], al[mt][2], al[mt][3], addr + TILE_BYTES);
            }
#pragma unroll
            for (int j = 0; j < 4; j++) {
                const uint32_t rowB = warp_n * 64 + (2 * j + (lane >> 4)) * 8 + (lane & 7);
                const uint32_t addr = sb + 2 * TILE_BYTES + rowB * ROWB + ks * 2
                                      + ((lane >> 3) & 1) * 16;
                uint32_t bh0, bh1, bh2, bh3, bl0, bl1, bl2, bl3;
                ldsm4(bh0, bh1, bh2, bh3, addr);
                ldsm4(bl0, bl1, bl2, bl3, addr + TILE_BYTES);
#pragma unroll
                for (int mt = 0; mt < 2; mt++) {
                    float* c0 = acc[mt][2 * j];
                    mma_bf16(c0[0], c0[1], c0[2], c0[3],
                             ah[mt][0], ah[mt][1], ah[mt][2], ah[mt][3], bh0, bh1);
                    mma_bf16(c0[0], c0[1], c0[2], c0[3],
                             ah[mt][0], ah[mt][1], ah[mt][2], ah[mt][3], bl0, bl1);
                    mma_bf16(c0[0], c0[1], c0[2], c0[3],
                             al[mt][0], al[mt][1], al[mt][2], al[mt][3], bh0, bh1);
                    float* c1 = acc[mt][2 * j + 1];
                    mma_bf16(c1[0], c1[1], c1[2], c1[3],
                             ah[mt][0], ah[mt][1], ah[mt][2], ah[mt][3], bh2, bh3);
                    mma_bf16(c1[0], c1[1], c1[2], c1[3],
                             ah[mt][0], ah[mt][1], ah[mt][2], ah[mt][3], bl2, bl3);
                    mma_bf16(c1[0], c1[1], c1[2], c1[3],
                             al[mt][0], al[mt][1], al[mt][2], al[mt][3], bh2, bh3);
                }
            }
        }
    };

    const int KT = CDIM / 32;   // 16
    load_stage(0, 0);
    asm volatile("cp.async.commit_group;" ::: "memory");

    for (int kt = 0; kt < KT; kt++) {
        asm volatile("cp.async.wait_group 0;" ::: "memory");
        __syncthreads();
        if (kt + 1 < KT) {
            load_stage((kt + 1) & 1, (kt + 1) * 32);
            asm volatile("cp.async.commit_group;" ::: "memory");
        }
        compute_stage(kt & 1);
        // no trailing barrier: next iteration's wait_group+sync covers reuse
    }

    // Epilogue (fragment layout identical to validated R6/R7 kernels)
    const int g = lane >> 2;
    const int q = lane & 3;
#pragma unroll
    for (int mt = 0; mt < 2; mt++) {
        const int m0 = bm * 128 + warp_m * 32 + mt * 16 + g;
#pragma unroll
        for (int nt = 0; nt < 8; nt++) {
            const int col0 = bn * 128 + warp_n * 64 + nt * 8 + 2 * q;
#pragma unroll
            for (int half = 0; half < 2; half++) {
                const int m = m0 + half * 8;
                const int b_idx = m / SEQ;
                const int n_idx = m - b_idx * SEQ;
#pragma unroll
                for (int e = 0; e < 2; e++) {
                    const int col = col0 + e;
                    float val = acc[mt][nt][half * 2 + e] + bias[col];
                    if (MODE == 0) {
                        const int s = col >> 9;          // 0:q 1:k 2:v
                        const int h = (col >> 5) & 15;
                        const int d = col & 31;
                        const size_t off =
                            ((((size_t)b_idx * NHEAD + h) * SEQ) + n_idx) * HD + d;
                        if (s == 0)      g_q[off] = val * SCALE;
                        else if (s == 1) g_k[off] = val;
                        else             g_v[off] = val;
                    } else {
                        Cout[(size_t)m * CDIM + col] = val;
                    }
                }
            }
        }
    }
}

// ---------------------------------------------------------------------------
// Attention: one block per (head, window). 256 threads.
// Register-tiled QK (4x4) and PV (4x2) to cut smem crossbar traffic ~3x.
// Padded strides; padded lanes carry garbage but are never read.
// ---------------------------------------------------------------------------
#define QS_STRIDE 33
#define S_STRIDE  52

__global__ __launch_bounds__(256)
void attn_kernel(const float* __restrict__ mask,
                 const float* __restrict__ table,
                 const int* __restrict__ relidx)
{
    const int h = blockIdx.x;
    const int b = blockIdx.y;
    const int tid = threadIdx.x;

    __shared__ float qs[52 * QS_STRIDE];
    __shared__ float ks[52 * QS_STRIDE];
    __shared__ float vs[52 * QS_STRIDE];
    __shared__ float bmask[SEQ * S_STRIDE];
    __shared__ float S[52 * S_STRIDE];

    const size_t base = (((size_t)b * NHEAD + h) * SEQ) * HD;

    for (int i = tid; i < SEQ * HD; i += 256) {
        const int r = i >> 5, c = i & 31;
        qs[r * QS_STRIDE + c] = g_q[base + i];
        ks[r * QS_STRIDE + c] = g_k[base + i];
        vs[r * QS_STRIDE + c] = g_v[base + i];
    }
    const float* mptr = mask + (size_t)(b & (NWIN - 1)) * SEQ * SEQ;
    for (int idx = tid; idx < SEQ * SEQ; idx += 256) {
        const int i = idx / SEQ;
        const int j = idx - i * SEQ;
        bmask[i * S_STRIDE + j] = table[relidx[idx] * NHEAD + h] + mptr[idx];
    }
    __syncthreads();

    // ---- QK: 13x13 grid of 4x4 tiles (169 units; one per thread) ----
    if (tid < 169) {
        const int i0 = (tid / 13) * 4;
        const int j0 = (tid - (tid / 13) * 13) * 4;
        float acc[4][4];
#pragma unroll
        for (int a = 0; a < 4; a++)
#pragma unroll
            for (int c = 0; c < 4; c++) acc[a][c] = 0.0f;
#pragma unroll
        for (int d = 0; d < HD; d++) {
            float qv[4], kv[4];
#pragma unroll
            for (int t = 0; t < 4; t++) {
                qv[t] = qs[(i0 + t) * QS_STRIDE + d];
                kv[t] = ks[(j0 + t) * QS_STRIDE + d];
            }
#pragma unroll
            for (int a = 0; a < 4; a++)
#pragma unroll
                for (int c = 0; c < 4; c++)
                    acc[a][c] = fmaf(qv[a], kv[c], acc[a][c]);
        }
#pragma unroll
        for (int a = 0; a < 4; a++) {
            const int i = i0 + a;
            if (i < SEQ) {
#pragma unroll
                for (int c = 0; c < 4; c++)
                    S[i * S_STRIDE + j0 + c] = acc[a][c] + bmask[i * S_STRIDE + j0 + c];
            }
        }
    }
    __syncthreads();

    // ---- softmax (one thread per row) ----
    if (tid < SEQ) {
        float mx = -1e30f;
        for (int j = 0; j < SEQ; j++) mx = fmaxf(mx, S[tid * S_STRIDE + j]);
        float sum = 0.0f;
        for (int j = 0; j < SEQ; j++) {
            const float e = __expf(S[tid * S_STRIDE + j] - mx);
            S[tid * S_STRIDE + j] = e;
            sum += e;
        }
        const float inv = 1.0f / sum;
        for (int j = 0; j < SEQ; j++) S[tid * S_STRIDE + j] *= inv;
    }
    __syncthreads();

    // ---- PV: 13 i-tiles x 16 d-tiles of 4i x 2d (208 units) ----
    if (tid < 208) {
        const int i0 = (tid / 16) * 4;
        const int d0 = (tid - (tid / 16) * 16) * 2;
        float acc[4][2];
#pragma unroll
        for (int a = 0; a < 4; a++) { acc[a][0] = 0.0f; acc[a][1] = 0.0f; }
        for (int j = 0; j < SEQ; j++) {
            const float v0 = vs[j * QS_STRIDE + d0];
            const float v1 = vs[j * QS_STRIDE + d0 + 1];
#pragma unroll
            for (int a = 0; a < 4; a++) {
                const float sv = S[(i0 + a) * S_STRIDE + j];
                acc[a][0] = fmaf(sv, v0, acc[a][0]);
                acc[a][1] = fmaf(sv, v1, acc[a][1]);
            }
        }
#pragma unroll
        for (int a = 0; a < 4; a++) {
            const int i = i0 + a;
            if (i < SEQ) {
#pragma unroll
                for (int e = 0; e < 2; e++) {
                    const float o = acc[a][e];
                    const size_t oo = ((size_t)b * SEQ + i) * CDIM + h * HD + d0 + e;
                    __nv_bfloat16 hi = __float2bfloat16(o);
                    g_oh[oo] = hi;
                    g_ol[oo] = __float2bfloat16(o - __bfloat162float(hi));
                }
            }
        }
    }
}

// ---------------------------------------------------------------------------
extern "C" void kernel_launch(void* const* d_in, const int* in_sizes, int n_in,
                              void* d_out, int out_size)
{
    const float* x      = nullptr;
    const float* mask   = nullptr;
    const float* qkv_w  = nullptr;
    const float* qkv_b  = nullptr;
    const float* proj_w = nullptr;
    const float* proj_b = nullptr;
    const float* table  = nullptr;
    const int*   relidx = nullptr;

    for (int i = 0; i < n_in; i++) {
        switch (in_sizes[i]) {
            case 51380224: x      = (const float*)d_in[i]; break;
            case 153664:   mask   = (const float*)d_in[i]; break;
            case 786432:   qkv_w  = (const float*)d_in[i]; break;
            case 1536:     qkv_b  = (const float*)d_in[i]; break;
            case 262144:   proj_w = (const float*)d_in[i]; break;
            case 512:      proj_b = (const float*)d_in[i]; break;
            case 2704:     table  = (const float*)d_in[i]; break;
            case 2401:     relidx = (const int*)  d_in[i]; break;
            default: break;
        }
    }
    float* out = (float*)d_out;

    cudaFuncSetAttribute(gemm_tc<0>, cudaFuncAttributeMaxDynamicSharedMemorySize, SMEM_DYN);
    cudaFuncSetAttribute(gemm_tc<1>, cudaFuncAttributeMaxDynamicSharedMemorySize, SMEM_DYN);

    // Pre-split conversions (hi/lo bf16)
    convert_split<0><<<(MROWS * CDIM / 4) / 256, 256>>>(x);
    convert_split<1><<<(QKVCOLS * CDIM / 4) / 256, 256>>>(qkv_w);
    convert_split<2><<<(CDIM * CDIM / 4) / 256, 256>>>(proj_w);

    {
        dim3 grid(QKVCOLS / 128, MROWS / 128);   // (12, 784)
        gemm_tc<0><<<grid, 256, SMEM_DYN>>>(qkv_b, nullptr);
    }
    {
        dim3 grid(NHEAD, B_TOT);
        attn_kernel<<<grid, 256>>>(mask, table, relidx);
    }
    {
        dim3 grid(CDIM / 128, MROWS / 128);      // (4, 784)
        gemm_tc<1><<<grid, 256, SMEM_DYN>>>(proj_b, out);
    }
}